// round 1
// baseline (speedup 1.0000x reference)
#include <cuda_runtime.h>

#define NF 64
#define NH 256
#define NB 8192

// Packed weights: pair (wl, wd) per (f,h); wl = exp(exu_w)*log2(e), wd = exp(exu_w)*dense_k.
// Stored as float4 (two h's per float4) for vectorized loads. 64KB*2 total.
__device__ float4 g_w4[NF * NH / 2];
__device__ float g_sumdb;

__global__ void prep_kernel(const float* __restrict__ exu_w,
                            const float* __restrict__ dense_k,
                            const float* __restrict__ dense_b) {
    int i = blockIdx.x * blockDim.x + threadIdx.x;
    if (i < NF * NH) {
        float ew = expf(exu_w[i]);  // accurate exp, precompute cost is trivial
        float2 v = make_float2(ew * 1.4426950408889634f, ew * dense_k[i]);
        reinterpret_cast<float2*>(g_w4)[i] = v;
    }
    if (blockIdx.x == 0 && threadIdx.x < 32) {
        float s = dense_b[threadIdx.x] + dense_b[threadIdx.x + 32];
        #pragma unroll
        for (int o = 16; o > 0; o >>= 1)
            s += __shfl_down_sync(0xffffffffu, s, o);
        if (threadIdx.x == 0) g_sumdb = s;
    }
}

__device__ __forceinline__ float ex2a(float x) {
    float y; asm("ex2.approx.f32 %0, %1;" : "=f"(y) : "f"(x)); return y;
}
__device__ __forceinline__ float rcpa(float x) {
    float y; asm("rcp.approx.f32 %0, %1;" : "=f"(y) : "f"(x)); return y;
}

// ratio = tanh(softplus(h)) with h = d*ew, computed as u/(u+2), u = t(t+2), t = e^h.
// arg clamped at 60 in exp2 domain: exp2(60)^2 ~ 1.3e36 finite, ratio -> 1.0f exactly.
#define MISH_TERM(ACC, D, WL, WD, FIRST)                         \
    do {                                                         \
        float _t  = ex2a(fminf((D) * (WL), 60.0f));              \
        float _t2 = _t + 2.0f;                                   \
        float _u  = _t * _t2;                                    \
        float _v  = fmaf(_t, _t2, 2.0f);                         \
        float _w  = _u * rcpa(_v);                               \
        if (FIRST) (ACC) = (WD) * _w;                            \
        else       (ACC) = fmaf((WD), _w, (ACC));                \
    } while (0)

// Block = 512 threads = 16 warps = 8 batch rows.
// Warp w: b_local = w>>1, h-half = w&1. Each lane owns 4 consecutive h's.
// X / exu_b loads are warp-uniform (broadcast); weight loads are coalesced LDG.128.
__global__ void __launch_bounds__(512, 2)
nam_kernel(const float* __restrict__ X,
           const float* __restrict__ exu_b,
           float* __restrict__ out) {
    const int tid  = threadIdx.x;
    const int lane = tid & 31;
    const int wid  = tid >> 5;
    const int b    = blockIdx.x * 8 + (wid >> 1);
    // float4 index base within a row of 128 float4s: covers h = 4*lane + 128*(wid&1) .. +3
    const int p0 = (wid & 1) * 64 + lane * 2;

    const float* xrow = X + b * NF;
    float acc = 0.0f;

    #pragma unroll 4
    for (int f = 0; f < NF; ++f) {
        float d = __ldg(xrow + f) - __ldg(exu_b + f);
        const float4* wrow = g_w4 + f * (NH / 2) + p0;
        float4 a = wrow[0];
        float4 c = wrow[1];
        float accf;
        MISH_TERM(accf, d, a.x, a.y, 1);
        MISH_TERM(accf, d, a.z, a.w, 0);
        MISH_TERM(accf, d, c.x, c.y, 0);
        MISH_TERM(accf, d, c.z, c.w, 0);
        acc = fmaf(d, accf, acc);  // d multiplied once per f, not per element
    }

    // warp reduction
    #pragma unroll
    for (int o = 16; o > 0; o >>= 1)
        acc += __shfl_down_sync(0xffffffffu, acc, o);

    __shared__ float sp[16];
    if (lane == 0) sp[wid] = acc;
    __syncthreads();
    if (tid < 8)
        out[blockIdx.x * 8 + tid] = sp[2 * tid] + sp[2 * tid + 1] + g_sumdb;
}

extern "C" void kernel_launch(void* const* d_in, const int* in_sizes, int n_in,
                              void* d_out, int out_size) {
    const float* X       = (const float*)d_in[0];
    const float* exu_w   = (const float*)d_in[1];
    const float* exu_b   = (const float*)d_in[2];
    const float* dense_k = (const float*)d_in[3];
    const float* dense_b = (const float*)d_in[4];
    float* out = (float*)d_out;

    (void)in_sizes; (void)n_in; (void)out_size;

    prep_kernel<<<(NF * NH + 255) / 256, 256>>>(exu_w, dense_k, dense_b);
    nam_kernel<<<NB / 8, 512>>>(X, exu_b, out);
}